// round 1
// baseline (speedup 1.0000x reference)
#include <cuda_runtime.h>
#include <cuda_bf16.h>

// CropAndResize: image [8,256,64,64] f32 NCHW, boxes [1000,4] f32 (y1,x1,y2,x2),
// box_ind [1000] i32. Output [1000,256,14,14] f32, TF-style bilinear with
// extrapolation_value = 0 for out-of-bounds sample coordinates.

namespace {
constexpr int C      = 256;
constexpr int H      = 64;
constexpr int W      = 64;
constexpr int CROP_H = 14;
constexpr int CROP_W = 14;
constexpr int PIX    = CROP_H * CROP_W;   // 196
constexpr int QUADS  = PIX / 4;           // 49 float4 per channel
}

__global__ void crop_resize_kernel(const float* __restrict__ img,
                                   const float4* __restrict__ boxes,
                                   const int* __restrict__ box_ind,
                                   float4* __restrict__ out,
                                   int total_quads)
{
    int idx = blockIdx.x * blockDim.x + threadIdx.x;
    if (idx >= total_quads) return;

    // idx -> (box, channel, quad)
    int box = idx / (C * QUADS);
    int rem = idx - box * (C * QUADS);
    int c   = rem / QUADS;
    int q   = rem - c * QUADS;

    float4 bb = boxes[box];          // y1, x1, y2, x2  (broadcast within warp)
    int    b  = box_ind[box];

    const float* __restrict__ plane = img + ((long)b * C + c) * (H * W);

    // Match reference rounding order: h_scale = ((y2-y1)*(H-1)) / (crop-1)
    float hs = ((bb.z - bb.x) * (float)(H - 1)) / (float)(CROP_H - 1);
    float ws = ((bb.w - bb.y) * (float)(W - 1)) / (float)(CROP_W - 1);
    float ybase = bb.x * (float)(H - 1);
    float xbase = bb.y * (float)(W - 1);

    float4 res;
    float* r = reinterpret_cast<float*>(&res);

    #pragma unroll
    for (int i = 0; i < 4; ++i) {
        int p  = 4 * q + i;
        int iy = p / CROP_W;
        int ix = p - iy * CROP_W;

        float in_y = ybase + (float)iy * hs;
        float in_x = xbase + (float)ix * ws;

        bool oob = (in_y < 0.0f) | (in_y > (float)(H - 1)) |
                   (in_x < 0.0f) | (in_x > (float)(W - 1));

        float tf = floorf(in_y);
        float lf = floorf(in_x);
        float yl = in_y - tf;
        float xl = in_x - lf;

        int ti = min(max((int)tf, 0), H - 1);
        int bi = min(max((int)tf + 1, 0), H - 1);
        int li = min(max((int)lf, 0), W - 1);
        int ri = min(max((int)lf + 1, 0), W - 1);

        int rowt = ti * W;
        int rowb = bi * W;

        float tl = __ldg(plane + rowt + li);
        float tr = __ldg(plane + rowt + ri);
        float bl = __ldg(plane + rowb + li);
        float br = __ldg(plane + rowb + ri);

        float top = tl + (tr - tl) * xl;
        float bot = bl + (br - bl) * xl;
        float v   = top + (bot - top) * yl;

        r[i] = oob ? 0.0f : v;
    }

    out[idx] = res;
}

extern "C" void kernel_launch(void* const* d_in, const int* in_sizes, int n_in,
                              void* d_out, int out_size)
{
    const float*  img     = (const float*)d_in[0];
    const float4* boxes   = (const float4*)d_in[1];
    const int*    box_ind = (const int*)d_in[2];
    float4*       out     = (float4*)d_out;

    int n_boxes     = in_sizes[2];              // 1000
    int total_quads = n_boxes * C * QUADS;      // 12,544,000

    int threads = 256;
    int blocks  = (total_quads + threads - 1) / threads;
    crop_resize_kernel<<<blocks, threads>>>(img, boxes, box_ind, out, total_quads);
}